// round 11
// baseline (speedup 1.0000x reference)
#include <cuda_runtime.h>
#include <cuda_bf16.h>
#include <cstdint>
#include <math.h>

#define TT 1024
#define BB 4
#define HH 1024
#define VV 32000
#define NBLK 128
#define UPB 8

typedef unsigned long long ull;

// ======================= helpers =======================
__device__ __forceinline__ uint32_t smem_to_u32(const void* p) {
    uint32_t a;
    asm("{ .reg .u64 t; cvta.to.shared.u64 t, %1; cvt.u32.u64 %0, t; }" : "=r"(a) : "l"(p));
    return a;
}
__device__ __forceinline__ void cp16(uint32_t dst, const void* src) {
    asm volatile("cp.async.cg.shared.global [%0], [%1], 16;" :: "r"(dst), "l"(src) : "memory");
}
#define CP_COMMIT() asm volatile("cp.async.commit_group;" ::: "memory")
#define CP_WAIT(n)  asm volatile("cp.async.wait_group %0;" :: "n"(n) : "memory")

#define LDSM_X4(r0, r1, r2, r3, addr) \
    asm volatile("ldmatrix.sync.aligned.m8n8.x4.shared.b16 {%0,%1,%2,%3}, [%4];" \
        : "=r"(r0), "=r"(r1), "=r"(r2), "=r"(r3) : "r"(addr))
#define MMA16816(c0, c1, c2, c3, a0, a1, a2, a3, b0, b1) \
    asm volatile("mma.sync.aligned.m16n8k16.row.col.f32.bf16.bf16.f32 " \
        "{%0,%1,%2,%3}, {%4,%5,%6,%7}, {%8,%9}, {%0,%1,%2,%3};" \
        : "+f"(c0), "+f"(c1), "+f"(c2), "+f"(c3) \
        : "r"(a0), "r"(a1), "r"(a2), "r"(a3), "r"(b0), "r"(b1))

// packed dual-fp32 FMA (FFMA2): acc.xy += w.xy * h.xy
#define FMA2(acc, w, h) \
    asm("fma.rn.f32x2 %0, %1, %2, %0;" : "+l"(acc) : "l"(w), "l"(h))
__device__ __forceinline__ float f2sum(ull v) {
    return __uint_as_float((unsigned)v) + __uint_as_float((unsigned)(v >> 32));
}

// ======================= scratch =======================
__device__ __nv_bfloat16 g_weh[(size_t)VV * HH];
__device__ __nv_bfloat16 g_wel[(size_t)VV * HH];
__device__ __nv_bfloat16 g_wihh[(size_t)2 * 4 * HH * HH];
__device__ __nv_bfloat16 g_wihl[(size_t)2 * 4 * HH * HH];
__device__ __nv_bfloat16 g_fh[(size_t)TT * BB * HH];
__device__ __nv_bfloat16 g_fl[(size_t)TT * BB * HH];
__device__ __nv_bfloat16 g_h0h[(size_t)TT * BB * HH];
__device__ __nv_bfloat16 g_h0l[(size_t)TT * BB * HH];
__device__ __nv_bfloat16 g_xnh[(size_t)TT * BB * HH];
__device__ __nv_bfloat16 g_xnl[(size_t)TT * BB * HH];
__device__ float g_gates[(size_t)TT * BB * 4 * HH];
__device__ float g_h0[(size_t)TT * BB * HH];
__device__ float g_h1[(size_t)TT * BB * HH];
__device__ unsigned g_flags[NBLK];

__device__ __forceinline__ void split_bf16(float v, __nv_bfloat16& hi, __nv_bfloat16& lo) {
    __nv_bfloat16 h = __float2bfloat16(v);
    hi = h;
    lo = __float2bfloat16(v - __bfloat162float(h));
}

// ======================= fp32 -> bf16 hi/lo split =======================
__global__ __launch_bounds__(256) void convsplit_kernel(
    const float* __restrict__ in, __nv_bfloat16* __restrict__ hi,
    __nv_bfloat16* __restrict__ lo, int n4)
{
    int i = blockIdx.x * blockDim.x + threadIdx.x;
    if (i >= n4) return;
    float4 v = ((const float4*)in)[i];
    __nv_bfloat16 h0, h1, h2, h3, l0, l1, l2, l3;
    split_bf16(v.x, h0, l0); split_bf16(v.y, h1, l1);
    split_bf16(v.z, h2, l2); split_bf16(v.w, h3, l3);
    ((__nv_bfloat162*)hi)[i * 2 + 0] = __nv_bfloat162(h0, h1);
    ((__nv_bfloat162*)hi)[i * 2 + 1] = __nv_bfloat162(h2, h3);
    ((__nv_bfloat162*)lo)[i * 2 + 0] = __nv_bfloat162(l0, l1);
    ((__nv_bfloat162*)lo)[i * 2 + 1] = __nv_bfloat162(l2, l3);
}

// ======================= embedding -> bf16 split, time-major =======================
__global__ __launch_bounds__(256) void embed_kernel(
    const int* __restrict__ ids, const float* __restrict__ we,
    const float* __restrict__ pe, __nv_bfloat16* __restrict__ oh,
    __nv_bfloat16* __restrict__ ol)
{
    int t = blockIdx.x, b = blockIdx.y;
    int id = ids[b * TT + t];
    const float4* w = (const float4*)(we + (size_t)id * HH);
    const float4* p = (const float4*)(pe + (size_t)t * HH);
    size_t row = ((size_t)t * BB + b) * HH;
    for (int i = threadIdx.x; i < HH / 4; i += blockDim.x) {
        float4 a = w[i], c = p[i];
        float4 v = make_float4(a.x + c.x, a.y + c.y, a.z + c.z, a.w + c.w);
        __nv_bfloat16 h0, h1, h2, h3, l0, l1, l2, l3;
        split_bf16(v.x, h0, l0); split_bf16(v.y, h1, l1);
        split_bf16(v.z, h2, l2); split_bf16(v.w, h3, l3);
        ((__nv_bfloat162*)(oh + row))[i * 2 + 0] = __nv_bfloat162(h0, h1);
        ((__nv_bfloat162*)(oh + row))[i * 2 + 1] = __nv_bfloat162(h2, h3);
        ((__nv_bfloat162*)(ol + row))[i * 2 + 0] = __nv_bfloat162(l0, l1);
        ((__nv_bfloat162*)(ol + row))[i * 2 + 1] = __nv_bfloat162(l2, l3);
    }
}

// ======================= HMMA split-bf16 NT GEMM (known-good, unchanged) =======================
#define TSTRIDE 40
#define TILE_E  (128 * TSTRIDE)
#define TILE_BYTES (TILE_E * 2)            // 10240
#define BUF_BYTES (4 * TILE_BYTES)         // 40960
#define GSMEM (2 * BUF_BYTES)              // 81920

__global__ __launch_bounds__(256, 2) void gemm_hmma_kernel(
    const __nv_bfloat16* __restrict__ Ah, const __nv_bfloat16* __restrict__ Al,
    const __nv_bfloat16* __restrict__ Bh, const __nv_bfloat16* __restrict__ Bl,
    const float* __restrict__ bias0, const float* __restrict__ bias1,
    float* __restrict__ C, int N)
{
    extern __shared__ __nv_bfloat16 sm[];
    const uint32_t sbase = smem_to_u32(sm);
    const int tid = threadIdx.x;
    const int lane = tid & 31;
    const int wid = tid >> 5;
    const int wm = wid & 3;
    const int wn = wid >> 2;
    const int bn = blockIdx.x << 7;
    const int bm = blockIdx.y << 7;

    float acc[2][8][4];
#pragma unroll
    for (int mt = 0; mt < 2; ++mt)
#pragma unroll
        for (int nt = 0; nt < 8; ++nt)
#pragma unroll
            for (int q = 0; q < 4; ++q) acc[mt][nt][q] = 0.f;

    const __nv_bfloat16* srcs[4] = { Ah, Al, Bh, Bl };
    const int rb[4] = { bm, bm, bn, bn };

    auto load_chunk = [&](int c) {
        uint32_t buf = sbase + (c & 1) * BUF_BYTES;
#pragma unroll
        for (int tsel = 0; tsel < 4; ++tsel) {
            uint32_t dst = buf + tsel * TILE_BYTES;
            const __nv_bfloat16* base = srcs[tsel];
#pragma unroll
            for (int i = 0; i < 2; ++i) {
                int s = tid + (i << 8);
                int row = s >> 2, k8 = s & 3;
                cp16(dst + row * (TSTRIDE * 2) + k8 * 16,
                     base + (size_t)(rb[tsel] + row) * 1024 + c * 32 + k8 * 8);
            }
        }
        CP_COMMIT();
    };

    load_chunk(0);

    for (int c = 0; c < 32; ++c) {
        if (c < 31) { load_chunk(c + 1); CP_WAIT(1); }
        else        { CP_WAIT(0); }
        __syncthreads();

        uint32_t buf = sbase + (c & 1) * BUF_BYTES;
        const int a_r = (lane & 15);
        const int a_k = (lane >> 4) << 3;
        const int b_n = ((lane >> 4) << 3) + (lane & 7);
        const int b_k = ((lane >> 3) & 1) << 3;

#pragma unroll
        for (int ks = 0; ks < 2; ++ks) {
            const int kbase = ks << 4;
            uint32_t ah[2][4], al[2][4], bh[16], bl[16];
#pragma unroll
            for (int mt = 0; mt < 2; ++mt) {
                int row = wm * 32 + mt * 16 + a_r;
                uint32_t addr = buf + (row * TSTRIDE + kbase + a_k) * 2;
                LDSM_X4(ah[mt][0], ah[mt][1], ah[mt][2], ah[mt][3], addr);
                LDSM_X4(al[mt][0], al[mt][1], al[mt][2], al[mt][3], addr + TILE_BYTES);
            }
#pragma unroll
            for (int np = 0; np < 4; ++np) {
                int nrow = wn * 64 + np * 16 + b_n;
                uint32_t addr = buf + 2 * TILE_BYTES + (nrow * TSTRIDE + kbase + b_k) * 2;
                LDSM_X4(bh[np * 4 + 0], bh[np * 4 + 1], bh[np * 4 + 2], bh[np * 4 + 3], addr);
                LDSM_X4(bl[np * 4 + 0], bl[np * 4 + 1], bl[np * 4 + 2], bl[np * 4 + 3],
                        addr + TILE_BYTES);
            }
#pragma unroll
            for (int mt = 0; mt < 2; ++mt)
#pragma unroll
                for (int nt = 0; nt < 8; ++nt) {
                    float* cc = acc[mt][nt];
                    MMA16816(cc[0], cc[1], cc[2], cc[3],
                             ah[mt][0], ah[mt][1], ah[mt][2], ah[mt][3],
                             bh[nt * 2], bh[nt * 2 + 1]);
                    MMA16816(cc[0], cc[1], cc[2], cc[3],
                             al[mt][0], al[mt][1], al[mt][2], al[mt][3],
                             bh[nt * 2], bh[nt * 2 + 1]);
                    MMA16816(cc[0], cc[1], cc[2], cc[3],
                             ah[mt][0], ah[mt][1], ah[mt][2], ah[mt][3],
                             bl[nt * 2], bl[nt * 2 + 1]);
                }
        }
        __syncthreads();
    }

#pragma unroll
    for (int mt = 0; mt < 2; ++mt) {
        int row0 = bm + wm * 32 + mt * 16 + (lane >> 2);
#pragma unroll
        for (int nt = 0; nt < 8; ++nt) {
            int col = bn + wn * 64 + nt * 8 + ((lane & 3) << 1);
            float b0v = 0.f, b1v = 0.f;
            if (bias0) {
                b0v = bias0[col] + bias1[col];
                b1v = bias0[col + 1] + bias1[col + 1];
            }
            float* c0 = C + (size_t)row0 * N + col;
            float* c1 = C + (size_t)(row0 + 8) * N + col;
            *(float2*)c0 = make_float2(acc[mt][nt][0] + b0v, acc[mt][nt][1] + b1v);
            *(float2*)c1 = make_float2(acc[mt][nt][2] + b0v, acc[mt][nt][3] + b1v);
        }
    }
}

// ======================= persistent LSTM recurrence (R9 compute + flag-array barrier) =======================
// Release: block blk stores flags[blk] = t+1 with st.release (128 distinct addresses
// -> no L2 atomic-ALU serialization). Wait: warp 0, lane l polls flags[4l..4l+3] via
// one volatile LDG.128; exit when __all_sync(min4 >= t); one fence.acq_rel on exit.
__device__ __forceinline__ float sigm(float x) { return 1.f / (1.f + expf(-x)); }

__global__ __launch_bounds__(256) void lstm_layer_kernel(
    const float* __restrict__ gates_in, const float* __restrict__ Whh,
    float* __restrict__ hout, unsigned* flags)
{
    extern __shared__ float smf[];
    float* Wsh  = smf;                      // [32][1028]
    float* hsh  = Wsh + 32 * 1028;          // [4][1024]
    float* part = hsh + 4 * 1024;           // [8][32][4]
    float* gsm  = part + 8 * 32 * 4;        // [32][4]
    float* csh  = gsm + 32 * 4;             // [32]

    const int tid = threadIdx.x;
    const int blk = blockIdx.x;
    const int u0 = blk * UPB;

#pragma unroll
    for (int r = 0; r < 32; ++r) {
        int g = r >> 3, u = r & 7;
        const float* src = Whh + (size_t)(g * HH + u0 + u) * HH;
        *(float4*)(Wsh + r * 1028 + tid * 4) = *(const float4*)(src + tid * 4);
    }
    if (tid < 32) csh[tid] = 0.f;
    for (int i = tid * 4; i < BB * HH; i += 1024)
        *(float4*)(hsh + i) = make_float4(0.f, 0.f, 0.f, 0.f);
    __syncthreads();

    const int j  = tid & 31;
    const int ks = tid >> 5;
    const int jj = tid >> 2, bb = tid & 3;
    const int gg = jj >> 3, uu = jj & 7;
    const float* gptr = gates_in + (size_t)bb * (4 * HH) + gg * HH + u0 + uu;
    const unsigned* fvec = flags + (size_t)(tid & 31) * 4;   // lane's 4 flags

    for (int t = 0; t < TT; ++t) {
        // prefetch this step's gate input (latency hides under the barrier wait)
        float gin = 0.f;
        if (tid < 128) gin = __ldg(gptr + (size_t)t * BB * 4 * HH);

        if (t > 0) {
            if (tid < 32) {
                unsigned tt = (unsigned)t;
                for (;;) {
                    unsigned v0, v1, v2, v3;
                    asm volatile("ld.volatile.global.v4.u32 {%0,%1,%2,%3}, [%4];"
                                 : "=r"(v0), "=r"(v1), "=r"(v2), "=r"(v3)
                                 : "l"(fvec));
                    unsigned mn = min(min(v0, v1), min(v2, v3));
                    if (__all_sync(0xffffffffu, mn >= tt)) break;
                }
                asm volatile("fence.acq_rel.gpu;" ::: "memory");
            }
            __syncthreads();
            const float* hp = hout + (size_t)(t - 1) * BB * HH;
            for (int i = tid * 4; i < BB * HH; i += 1024)
                *(float4*)(hsh + i) = __ldcg((const float4*)(hp + i));
            __syncthreads();
        }

        // packed f32x2 partial dots: acc.xy[b] += W[j][k,k+1] * h[b][k,k+1]
        {
            const float* wr = Wsh + j * 1028 + (ks << 7);
            const float* hb = hsh + (ks << 7);
            ull a0 = 0ull, a1 = 0ull, a2 = 0ull, a3 = 0ull;
#pragma unroll 8
            for (int k = 0; k < 128; k += 4) {
                ulonglong2 wv = *(const ulonglong2*)(wr + k);
                ulonglong2 x0 = *(const ulonglong2*)(hb + k);
                ulonglong2 x1 = *(const ulonglong2*)(hb + 1024 + k);
                ulonglong2 x2 = *(const ulonglong2*)(hb + 2048 + k);
                ulonglong2 x3 = *(const ulonglong2*)(hb + 3072 + k);
                FMA2(a0, wv.x, x0.x); FMA2(a0, wv.y, x0.y);
                FMA2(a1, wv.x, x1.x); FMA2(a1, wv.y, x1.y);
                FMA2(a2, wv.x, x2.x); FMA2(a2, wv.y, x2.y);
                FMA2(a3, wv.x, x3.x); FMA2(a3, wv.y, x3.y);
            }
            *(float4*)(part + ((ks << 5) + j) * 4) =
                make_float4(f2sum(a0), f2sum(a1), f2sum(a2), f2sum(a3));
        }
        __syncthreads();

        if (tid < 128) {
            float s = gin;
#pragma unroll
            for (int q = 0; q < 8; ++q) s += part[((q << 5) + jj) * 4 + bb];
            gsm[jj * 4 + bb] = s;
        }
        __syncthreads();

        if (tid < 32) {
            int u = tid >> 2, b = tid & 3;
            float gi = gsm[(0 * 8 + u) * 4 + b];
            float gf = gsm[(1 * 8 + u) * 4 + b];
            float gc = gsm[(2 * 8 + u) * 4 + b];
            float go = gsm[(3 * 8 + u) * 4 + b];
            float cc = csh[tid];
            float cn = sigm(gf) * cc + sigm(gi) * tanhf(gc);
            float hn = sigm(go) * tanhf(cn);
            csh[tid] = cn;
            hout[((size_t)t * BB + b) * HH + u0 + u] = hn;
        }
        __syncthreads();   // all h-stores of this block happen-before the release below
        if (tid == 0) {
            asm volatile("st.release.gpu.global.u32 [%0], %1;"
                         :: "l"(flags + blk), "r"((unsigned)(t + 1)) : "memory");
        }
    }
}

__global__ void reset_flags_kernel(unsigned* f)
{
    if (threadIdx.x < NBLK) f[threadIdx.x] = 0u;
}

// ======================= LayerNorm -> bf16 split, batch-major =======================
__global__ __launch_bounds__(256) void layernorm_kernel(
    const float* __restrict__ in, const float* __restrict__ w,
    const float* __restrict__ bv, __nv_bfloat16* __restrict__ oh,
    __nv_bfloat16* __restrict__ ol)
{
    int t = blockIdx.x, b = blockIdx.y;
    const float* x = in + ((size_t)t * BB + b) * HH;
    size_t orow = ((size_t)b * TT + t) * HH;
    __shared__ float row[HH];
    __shared__ float red[8];
    __shared__ float stat[2];
    int tid = threadIdx.x;

    float s = 0.f;
    for (int i = tid; i < HH; i += 256) { float v = x[i]; row[i] = v; s += v; }
#pragma unroll
    for (int off = 16; off; off >>= 1) s += __shfl_xor_sync(0xffffffffu, s, off);
    if ((tid & 31) == 0) red[tid >> 5] = s;
    __syncthreads();
    if (tid == 0) {
        float tot = 0.f;
        for (int i = 0; i < 8; ++i) tot += red[i];
        stat[0] = tot * (1.f / HH);
    }
    __syncthreads();
    float mu = stat[0];
    float v2 = 0.f;
    for (int i = tid; i < HH; i += 256) { float d = row[i] - mu; v2 += d * d; }
#pragma unroll
    for (int off = 16; off; off >>= 1) v2 += __shfl_xor_sync(0xffffffffu, v2, off);
    __syncthreads();
    if ((tid & 31) == 0) red[tid >> 5] = v2;
    __syncthreads();
    if (tid == 0) {
        float tot = 0.f;
        for (int i = 0; i < 8; ++i) tot += red[i];
        stat[1] = rsqrtf(tot * (1.f / HH) + 1e-5f);
    }
    __syncthreads();
    float inv = stat[1];
    for (int i = tid; i < HH; i += 256) {
        float v = (row[i] - mu) * inv * w[i] + bv[i];
        __nv_bfloat16 hi, lo;
        split_bf16(v, hi, lo);
        oh[orow + i] = hi;
        ol[orow + i] = lo;
    }
}

// ======================= launch =======================
extern "C" void kernel_launch(void* const* d_in, const int* in_sizes, int n_in,
                              void* d_out, int out_size)
{
    (void)in_sizes; (void)n_in; (void)out_size;
    const int*   ids = (const int*)d_in[0];
    const float* we  = (const float*)d_in[1];
    const float* pe  = (const float*)d_in[2];
    const float* Wih = (const float*)d_in[3];
    const float* Whh = (const float*)d_in[4];
    const float* bih = (const float*)d_in[5];
    const float* bhh = (const float*)d_in[6];
    const float* lnw = (const float*)d_in[7];
    const float* lnb = (const float*)d_in[8];
    float* out = (float*)d_out;

    __nv_bfloat16 *weh, *wel, *wihh, *wihl, *fh, *fl, *h0h, *h0l, *xnh, *xnl;
    float *gates, *h0, *h1; unsigned* flags;
    cudaGetSymbolAddress((void**)&weh,  g_weh);
    cudaGetSymbolAddress((void**)&wel,  g_wel);
    cudaGetSymbolAddress((void**)&wihh, g_wihh);
    cudaGetSymbolAddress((void**)&wihl, g_wihl);
    cudaGetSymbolAddress((void**)&fh,   g_fh);
    cudaGetSymbolAddress((void**)&fl,   g_fl);
    cudaGetSymbolAddress((void**)&h0h,  g_h0h);
    cudaGetSymbolAddress((void**)&h0l,  g_h0l);
    cudaGetSymbolAddress((void**)&xnh,  g_xnh);
    cudaGetSymbolAddress((void**)&xnl,  g_xnl);
    cudaGetSymbolAddress((void**)&gates, g_gates);
    cudaGetSymbolAddress((void**)&h0,    g_h0);
    cudaGetSymbolAddress((void**)&h1,    g_h1);
    cudaGetSymbolAddress((void**)&flags, g_flags);

    size_t lsmem = (size_t)(32 * 1028 + 4 * 1024 + 8 * 32 * 4 + 32 * 4 + 32) * sizeof(float);
    cudaFuncSetAttribute(lstm_layer_kernel,
                         cudaFuncAttributeMaxDynamicSharedMemorySize, (int)lsmem);
    cudaFuncSetAttribute(gemm_hmma_kernel,
                         cudaFuncAttributeMaxDynamicSharedMemorySize, GSMEM);

    // weight/input splits
    convsplit_kernel<<<(VV * HH / 4 + 255) / 256, 256>>>(we, weh, wel, VV * HH / 4);
    convsplit_kernel<<<(2 * 4 * HH * HH / 4 + 255) / 256, 256>>>(Wih, wihh, wihl,
                                                                 2 * 4 * HH * HH / 4);
    embed_kernel<<<dim3(TT, BB), 256>>>(ids, we, pe, fh, fl);

    // layer0 input gates
    gemm_hmma_kernel<<<dim3(4 * HH / 128, TT * BB / 128), 256, GSMEM>>>(
        fh, fl, wihh, wihl, bih, bhh, gates, 4 * HH);
    reset_flags_kernel<<<1, NBLK>>>(flags);
    lstm_layer_kernel<<<NBLK, 256, lsmem>>>(gates, Whh, h0, flags);

    // layer1
    convsplit_kernel<<<(TT * BB * HH / 4 + 255) / 256, 256>>>(h0, h0h, h0l, TT * BB * HH / 4);
    gemm_hmma_kernel<<<dim3(4 * HH / 128, TT * BB / 128), 256, GSMEM>>>(
        h0h, h0l, wihh + (size_t)4 * HH * HH, wihl + (size_t)4 * HH * HH,
        bih + 4 * HH, bhh + 4 * HH, gates, 4 * HH);
    reset_flags_kernel<<<1, NBLK>>>(flags);
    lstm_layer_kernel<<<NBLK, 256, lsmem>>>(gates, Whh + (size_t)4 * HH * HH, h1, flags);

    // layernorm + head
    layernorm_kernel<<<dim3(TT, BB), 256>>>(h1, lnw, lnb, xnh, xnl);
    gemm_hmma_kernel<<<dim3(VV / 128, TT * BB / 128), 256, GSMEM>>>(
        xnh, xnl, weh, wel, nullptr, nullptr, out, VV);
}

// round 12
// speedup vs baseline: 1.0328x; 1.0328x over previous
#include <cuda_runtime.h>
#include <cuda_bf16.h>
#include <cstdint>
#include <math.h>

#define TT 1024
#define BB 4
#define HH 1024
#define VV 32000
#define NBLK 128
#define UPB 8
#define NCTR 8            // sync counters, one per 16 blocks, 128B apart

typedef unsigned long long ull;

// ======================= helpers =======================
__device__ __forceinline__ uint32_t smem_to_u32(const void* p) {
    uint32_t a;
    asm("{ .reg .u64 t; cvta.to.shared.u64 t, %1; cvt.u32.u64 %0, t; }" : "=r"(a) : "l"(p));
    return a;
}
__device__ __forceinline__ void cp16(uint32_t dst, const void* src) {
    asm volatile("cp.async.cg.shared.global [%0], [%1], 16;" :: "r"(dst), "l"(src) : "memory");
}
#define CP_COMMIT() asm volatile("cp.async.commit_group;" ::: "memory")
#define CP_WAIT(n)  asm volatile("cp.async.wait_group %0;" :: "n"(n) : "memory")

#define LDSM_X4(r0, r1, r2, r3, addr) \
    asm volatile("ldmatrix.sync.aligned.m8n8.x4.shared.b16 {%0,%1,%2,%3}, [%4];" \
        : "=r"(r0), "=r"(r1), "=r"(r2), "=r"(r3) : "r"(addr))
#define MMA16816(c0, c1, c2, c3, a0, a1, a2, a3, b0, b1) \
    asm volatile("mma.sync.aligned.m16n8k16.row.col.f32.bf16.bf16.f32 " \
        "{%0,%1,%2,%3}, {%4,%5,%6,%7}, {%8,%9}, {%0,%1,%2,%3};" \
        : "+f"(c0), "+f"(c1), "+f"(c2), "+f"(c3) \
        : "r"(a0), "r"(a1), "r"(a2), "r"(a3), "r"(b0), "r"(b1))

// packed dual-fp32 FMA (FFMA2): acc.xy += w.xy * h.xy
#define FMA2(acc, w, h) \
    asm("fma.rn.f32x2 %0, %1, %2, %0;" : "+l"(acc) : "l"(w), "l"(h))
__device__ __forceinline__ float f2sum(ull v) {
    return __uint_as_float((unsigned)v) + __uint_as_float((unsigned)(v >> 32));
}

// ======================= scratch =======================
__device__ __nv_bfloat16 g_weh[(size_t)VV * HH];
__device__ __nv_bfloat16 g_wel[(size_t)VV * HH];
__device__ __nv_bfloat16 g_wihh[(size_t)2 * 4 * HH * HH];
__device__ __nv_bfloat16 g_wihl[(size_t)2 * 4 * HH * HH];
__device__ __nv_bfloat16 g_fh[(size_t)TT * BB * HH];
__device__ __nv_bfloat16 g_fl[(size_t)TT * BB * HH];
__device__ __nv_bfloat16 g_h0h[(size_t)TT * BB * HH];
__device__ __nv_bfloat16 g_h0l[(size_t)TT * BB * HH];
__device__ __nv_bfloat16 g_xnh[(size_t)TT * BB * HH];
__device__ __nv_bfloat16 g_xnl[(size_t)TT * BB * HH];
__device__ float g_gates[(size_t)TT * BB * 4 * HH];
__device__ float g_h0[(size_t)TT * BB * HH];
__device__ float g_h1[(size_t)TT * BB * HH];
__device__ unsigned g_counters[NCTR * 32];     // 128B apart -> distinct L2 lines

__device__ __forceinline__ void split_bf16(float v, __nv_bfloat16& hi, __nv_bfloat16& lo) {
    __nv_bfloat16 h = __float2bfloat16(v);
    hi = h;
    lo = __float2bfloat16(v - __bfloat162float(h));
}

// ======================= fp32 -> bf16 hi/lo split =======================
__global__ __launch_bounds__(256) void convsplit_kernel(
    const float* __restrict__ in, __nv_bfloat16* __restrict__ hi,
    __nv_bfloat16* __restrict__ lo, int n4)
{
    int i = blockIdx.x * blockDim.x + threadIdx.x;
    if (i >= n4) return;
    float4 v = ((const float4*)in)[i];
    __nv_bfloat16 h0, h1, h2, h3, l0, l1, l2, l3;
    split_bf16(v.x, h0, l0); split_bf16(v.y, h1, l1);
    split_bf16(v.z, h2, l2); split_bf16(v.w, h3, l3);
    ((__nv_bfloat162*)hi)[i * 2 + 0] = __nv_bfloat162(h0, h1);
    ((__nv_bfloat162*)hi)[i * 2 + 1] = __nv_bfloat162(h2, h3);
    ((__nv_bfloat162*)lo)[i * 2 + 0] = __nv_bfloat162(l0, l1);
    ((__nv_bfloat162*)lo)[i * 2 + 1] = __nv_bfloat162(l2, l3);
}

// ======================= embedding -> bf16 split, time-major =======================
__global__ __launch_bounds__(256) void embed_kernel(
    const int* __restrict__ ids, const float* __restrict__ we,
    const float* __restrict__ pe, __nv_bfloat16* __restrict__ oh,
    __nv_bfloat16* __restrict__ ol)
{
    int t = blockIdx.x, b = blockIdx.y;
    int id = ids[b * TT + t];
    const float4* w = (const float4*)(we + (size_t)id * HH);
    const float4* p = (const float4*)(pe + (size_t)t * HH);
    size_t row = ((size_t)t * BB + b) * HH;
    for (int i = threadIdx.x; i < HH / 4; i += blockDim.x) {
        float4 a = w[i], c = p[i];
        float4 v = make_float4(a.x + c.x, a.y + c.y, a.z + c.z, a.w + c.w);
        __nv_bfloat16 h0, h1, h2, h3, l0, l1, l2, l3;
        split_bf16(v.x, h0, l0); split_bf16(v.y, h1, l1);
        split_bf16(v.z, h2, l2); split_bf16(v.w, h3, l3);
        ((__nv_bfloat162*)(oh + row))[i * 2 + 0] = __nv_bfloat162(h0, h1);
        ((__nv_bfloat162*)(oh + row))[i * 2 + 1] = __nv_bfloat162(h2, h3);
        ((__nv_bfloat162*)(ol + row))[i * 2 + 0] = __nv_bfloat162(l0, l1);
        ((__nv_bfloat162*)(ol + row))[i * 2 + 1] = __nv_bfloat162(l2, l3);
    }
}

// ======================= HMMA split-bf16 NT GEMM (known-good, unchanged) =======================
#define TSTRIDE 40
#define TILE_E  (128 * TSTRIDE)
#define TILE_BYTES (TILE_E * 2)            // 10240
#define BUF_BYTES (4 * TILE_BYTES)         // 40960
#define GSMEM (2 * BUF_BYTES)              // 81920

__global__ __launch_bounds__(256, 2) void gemm_hmma_kernel(
    const __nv_bfloat16* __restrict__ Ah, const __nv_bfloat16* __restrict__ Al,
    const __nv_bfloat16* __restrict__ Bh, const __nv_bfloat16* __restrict__ Bl,
    const float* __restrict__ bias0, const float* __restrict__ bias1,
    float* __restrict__ C, int N)
{
    extern __shared__ __nv_bfloat16 sm[];
    const uint32_t sbase = smem_to_u32(sm);
    const int tid = threadIdx.x;
    const int lane = tid & 31;
    const int wid = tid >> 5;
    const int wm = wid & 3;
    const int wn = wid >> 2;
    const int bn = blockIdx.x << 7;
    const int bm = blockIdx.y << 7;

    float acc[2][8][4];
#pragma unroll
    for (int mt = 0; mt < 2; ++mt)
#pragma unroll
        for (int nt = 0; nt < 8; ++nt)
#pragma unroll
            for (int q = 0; q < 4; ++q) acc[mt][nt][q] = 0.f;

    const __nv_bfloat16* srcs[4] = { Ah, Al, Bh, Bl };
    const int rb[4] = { bm, bm, bn, bn };

    auto load_chunk = [&](int c) {
        uint32_t buf = sbase + (c & 1) * BUF_BYTES;
#pragma unroll
        for (int tsel = 0; tsel < 4; ++tsel) {
            uint32_t dst = buf + tsel * TILE_BYTES;
            const __nv_bfloat16* base = srcs[tsel];
#pragma unroll
            for (int i = 0; i < 2; ++i) {
                int s = tid + (i << 8);
                int row = s >> 2, k8 = s & 3;
                cp16(dst + row * (TSTRIDE * 2) + k8 * 16,
                     base + (size_t)(rb[tsel] + row) * 1024 + c * 32 + k8 * 8);
            }
        }
        CP_COMMIT();
    };

    load_chunk(0);

    for (int c = 0; c < 32; ++c) {
        if (c < 31) { load_chunk(c + 1); CP_WAIT(1); }
        else        { CP_WAIT(0); }
        __syncthreads();

        uint32_t buf = sbase + (c & 1) * BUF_BYTES;
        const int a_r = (lane & 15);
        const int a_k = (lane >> 4) << 3;
        const int b_n = ((lane >> 4) << 3) + (lane & 7);
        const int b_k = ((lane >> 3) & 1) << 3;

#pragma unroll
        for (int ks = 0; ks < 2; ++ks) {
            const int kbase = ks << 4;
            uint32_t ah[2][4], al[2][4], bh[16], bl[16];
#pragma unroll
            for (int mt = 0; mt < 2; ++mt) {
                int row = wm * 32 + mt * 16 + a_r;
                uint32_t addr = buf + (row * TSTRIDE + kbase + a_k) * 2;
                LDSM_X4(ah[mt][0], ah[mt][1], ah[mt][2], ah[mt][3], addr);
                LDSM_X4(al[mt][0], al[mt][1], al[mt][2], al[mt][3], addr + TILE_BYTES);
            }
#pragma unroll
            for (int np = 0; np < 4; ++np) {
                int nrow = wn * 64 + np * 16 + b_n;
                uint32_t addr = buf + 2 * TILE_BYTES + (nrow * TSTRIDE + kbase + b_k) * 2;
                LDSM_X4(bh[np * 4 + 0], bh[np * 4 + 1], bh[np * 4 + 2], bh[np * 4 + 3], addr);
                LDSM_X4(bl[np * 4 + 0], bl[np * 4 + 1], bl[np * 4 + 2], bl[np * 4 + 3],
                        addr + TILE_BYTES);
            }
#pragma unroll
            for (int mt = 0; mt < 2; ++mt)
#pragma unroll
                for (int nt = 0; nt < 8; ++nt) {
                    float* cc = acc[mt][nt];
                    MMA16816(cc[0], cc[1], cc[2], cc[3],
                             ah[mt][0], ah[mt][1], ah[mt][2], ah[mt][3],
                             bh[nt * 2], bh[nt * 2 + 1]);
                    MMA16816(cc[0], cc[1], cc[2], cc[3],
                             al[mt][0], al[mt][1], al[mt][2], al[mt][3],
                             bh[nt * 2], bh[nt * 2 + 1]);
                    MMA16816(cc[0], cc[1], cc[2], cc[3],
                             ah[mt][0], ah[mt][1], ah[mt][2], ah[mt][3],
                             bl[nt * 2], bl[nt * 2 + 1]);
                }
        }
        __syncthreads();
    }

#pragma unroll
    for (int mt = 0; mt < 2; ++mt) {
        int row0 = bm + wm * 32 + mt * 16 + (lane >> 2);
#pragma unroll
        for (int nt = 0; nt < 8; ++nt) {
            int col = bn + wn * 64 + nt * 8 + ((lane & 3) << 1);
            float b0v = 0.f, b1v = 0.f;
            if (bias0) {
                b0v = bias0[col] + bias1[col];
                b1v = bias0[col + 1] + bias1[col + 1];
            }
            float* c0 = C + (size_t)row0 * N + col;
            float* c1 = C + (size_t)(row0 + 8) * N + col;
            *(float2*)c0 = make_float2(acc[mt][nt][0] + b0v, acc[mt][nt][1] + b1v);
            *(float2*)c1 = make_float2(acc[mt][nt][2] + b0v, acc[mt][nt][3] + b1v);
        }
    }
}

// ======================= persistent LSTM recurrence (R9 compute + 8-counter barrier) =======================
// Release: block blk red.release-adds counter[blk&7] (8 L2 lines, 16 arrivals each ->
// parallel drain). Wait: lanes 0-7 of warp 0 each acquire-poll one counter until all
// reach 16*t (per-line poller count = 128, same as proven R9 load).
__device__ __forceinline__ float sigm(float x) { return 1.f / (1.f + expf(-x)); }

__global__ __launch_bounds__(256) void lstm_layer_kernel(
    const float* __restrict__ gates_in, const float* __restrict__ Whh,
    float* __restrict__ hout, unsigned* counters)
{
    extern __shared__ float smf[];
    float* Wsh  = smf;                      // [32][1028]
    float* hsh  = Wsh + 32 * 1028;          // [4][1024]
    float* part = hsh + 4 * 1024;           // [8][32][4]
    float* gsm  = part + 8 * 32 * 4;        // [32][4]
    float* csh  = gsm + 32 * 4;             // [32]

    const int tid = threadIdx.x;
    const int blk = blockIdx.x;
    const int u0 = blk * UPB;

#pragma unroll
    for (int r = 0; r < 32; ++r) {
        int g = r >> 3, u = r & 7;
        const float* src = Whh + (size_t)(g * HH + u0 + u) * HH;
        *(float4*)(Wsh + r * 1028 + tid * 4) = *(const float4*)(src + tid * 4);
    }
    if (tid < 32) csh[tid] = 0.f;
    for (int i = tid * 4; i < BB * HH; i += 1024)
        *(float4*)(hsh + i) = make_float4(0.f, 0.f, 0.f, 0.f);
    __syncthreads();

    const int j  = tid & 31;
    const int ks = tid >> 5;
    const int jj = tid >> 2, bb = tid & 3;
    const int gg = jj >> 3, uu = jj & 7;
    const float* gptr = gates_in + (size_t)bb * (4 * HH) + gg * HH + u0 + uu;
    unsigned* relctr = counters + (size_t)(blk & (NCTR - 1)) * 32;
    const unsigned* myctr = counters + (size_t)(tid & 31) * 32;   // lanes 0-7 valid

    for (int t = 0; t < TT; ++t) {
        // prefetch this step's gate input (latency hides under the barrier wait)
        float gin = 0.f;
        if (tid < 128) gin = __ldg(gptr + (size_t)t * BB * 4 * HH);

        if (t > 0) {
            if (tid < NCTR) {
                unsigned tgt = (unsigned)(NBLK / NCTR) * (unsigned)t;
                unsigned v;
                do {
                    asm volatile("ld.acquire.gpu.global.u32 %0, [%1];"
                                 : "=r"(v) : "l"(myctr));
                } while (__any_sync((1u << NCTR) - 1u, v < tgt));
            }
            __syncthreads();
            const float* hp = hout + (size_t)(t - 1) * BB * HH;
            for (int i = tid * 4; i < BB * HH; i += 1024)
                *(float4*)(hsh + i) = __ldcg((const float4*)(hp + i));
            __syncthreads();
        }

        // packed f32x2 partial dots: acc.xy[b] += W[j][k,k+1] * h[b][k,k+1]
        {
            const float* wr = Wsh + j * 1028 + (ks << 7);
            const float* hb = hsh + (ks << 7);
            ull a0 = 0ull, a1 = 0ull, a2 = 0ull, a3 = 0ull;
#pragma unroll 8
            for (int k = 0; k < 128; k += 4) {
                ulonglong2 wv = *(const ulonglong2*)(wr + k);
                ulonglong2 x0 = *(const ulonglong2*)(hb + k);
                ulonglong2 x1 = *(const ulonglong2*)(hb + 1024 + k);
                ulonglong2 x2 = *(const ulonglong2*)(hb + 2048 + k);
                ulonglong2 x3 = *(const ulonglong2*)(hb + 3072 + k);
                FMA2(a0, wv.x, x0.x); FMA2(a0, wv.y, x0.y);
                FMA2(a1, wv.x, x1.x); FMA2(a1, wv.y, x1.y);
                FMA2(a2, wv.x, x2.x); FMA2(a2, wv.y, x2.y);
                FMA2(a3, wv.x, x3.x); FMA2(a3, wv.y, x3.y);
            }
            *(float4*)(part + ((ks << 5) + j) * 4) =
                make_float4(f2sum(a0), f2sum(a1), f2sum(a2), f2sum(a3));
        }
        __syncthreads();

        if (tid < 128) {
            float s = gin;
#pragma unroll
            for (int q = 0; q < 8; ++q) s += part[((q << 5) + jj) * 4 + bb];
            gsm[jj * 4 + bb] = s;
        }
        __syncthreads();

        if (tid < 32) {
            int u = tid >> 2, b = tid & 3;
            float gi = gsm[(0 * 8 + u) * 4 + b];
            float gf = gsm[(1 * 8 + u) * 4 + b];
            float gc = gsm[(2 * 8 + u) * 4 + b];
            float go = gsm[(3 * 8 + u) * 4 + b];
            float cc = csh[tid];
            float cn = sigm(gf) * cc + sigm(gi) * tanhf(gc);
            float hn = sigm(go) * tanhf(cn);
            csh[tid] = cn;
            hout[((size_t)t * BB + b) * HH + u0 + u] = hn;
        }
        __syncthreads();   // all h-stores of this block happen-before the release below
        if (tid == 0) {
            asm volatile("red.release.gpu.global.add.u32 [%0], %1;"
                         :: "l"(relctr), "r"(1u) : "memory");
        }
    }
}

__global__ void reset_counters_kernel(unsigned* c)
{
    if (threadIdx.x < NCTR * 32) c[threadIdx.x] = 0u;
}

// ======================= LayerNorm -> bf16 split, batch-major =======================
__global__ __launch_bounds__(256) void layernorm_kernel(
    const float* __restrict__ in, const float* __restrict__ w,
    const float* __restrict__ bv, __nv_bfloat16* __restrict__ oh,
    __nv_bfloat16* __restrict__ ol)
{
    int t = blockIdx.x, b = blockIdx.y;
    const float* x = in + ((size_t)t * BB + b) * HH;
    size_t orow = ((size_t)b * TT + t) * HH;
    __shared__ float row[HH];
    __shared__ float red[8];
    __shared__ float stat[2];
    int tid = threadIdx.x;

    float s = 0.f;
    for (int i = tid; i < HH; i += 256) { float v = x[i]; row[i] = v; s += v; }
#pragma unroll
    for (int off = 16; off; off >>= 1) s += __shfl_xor_sync(0xffffffffu, s, off);
    if ((tid & 31) == 0) red[tid >> 5] = s;
    __syncthreads();
    if (tid == 0) {
        float tot = 0.f;
        for (int i = 0; i < 8; ++i) tot += red[i];
        stat[0] = tot * (1.f / HH);
    }
    __syncthreads();
    float mu = stat[0];
    float v2 = 0.f;
    for (int i = tid; i < HH; i += 256) { float d = row[i] - mu; v2 += d * d; }
#pragma unroll
    for (int off = 16; off; off >>= 1) v2 += __shfl_xor_sync(0xffffffffu, v2, off);
    __syncthreads();
    if ((tid & 31) == 0) red[tid >> 5] = v2;
    __syncthreads();
    if (tid == 0) {
        float tot = 0.f;
        for (int i = 0; i < 8; ++i) tot += red[i];
        stat[1] = rsqrtf(tot * (1.f / HH) + 1e-5f);
    }
    __syncthreads();
    float inv = stat[1];
    for (int i = tid; i < HH; i += 256) {
        float v = (row[i] - mu) * inv * w[i] + bv[i];
        __nv_bfloat16 hi, lo;
        split_bf16(v, hi, lo);
        oh[orow + i] = hi;
        ol[orow + i] = lo;
    }
}

// ======================= launch =======================
extern "C" void kernel_launch(void* const* d_in, const int* in_sizes, int n_in,
                              void* d_out, int out_size)
{
    (void)in_sizes; (void)n_in; (void)out_size;
    const int*   ids = (const int*)d_in[0];
    const float* we  = (const float*)d_in[1];
    const float* pe  = (const float*)d_in[2];
    const float* Wih = (const float*)d_in[3];
    const float* Whh = (const float*)d_in[4];
    const float* bih = (const float*)d_in[5];
    const float* bhh = (const float*)d_in[6];
    const float* lnw = (const float*)d_in[7];
    const float* lnb = (const float*)d_in[8];
    float* out = (float*)d_out;

    __nv_bfloat16 *weh, *wel, *wihh, *wihl, *fh, *fl, *h0h, *h0l, *xnh, *xnl;
    float *gates, *h0, *h1; unsigned* counters;
    cudaGetSymbolAddress((void**)&weh,  g_weh);
    cudaGetSymbolAddress((void**)&wel,  g_wel);
    cudaGetSymbolAddress((void**)&wihh, g_wihh);
    cudaGetSymbolAddress((void**)&wihl, g_wihl);
    cudaGetSymbolAddress((void**)&fh,   g_fh);
    cudaGetSymbolAddress((void**)&fl,   g_fl);
    cudaGetSymbolAddress((void**)&h0h,  g_h0h);
    cudaGetSymbolAddress((void**)&h0l,  g_h0l);
    cudaGetSymbolAddress((void**)&xnh,  g_xnh);
    cudaGetSymbolAddress((void**)&xnl,  g_xnl);
    cudaGetSymbolAddress((void**)&gates, g_gates);
    cudaGetSymbolAddress((void**)&h0,    g_h0);
    cudaGetSymbolAddress((void**)&h1,    g_h1);
    cudaGetSymbolAddress((void**)&counters, g_counters);

    size_t lsmem = (size_t)(32 * 1028 + 4 * 1024 + 8 * 32 * 4 + 32 * 4 + 32) * sizeof(float);
    cudaFuncSetAttribute(lstm_layer_kernel,
                         cudaFuncAttributeMaxDynamicSharedMemorySize, (int)lsmem);
    cudaFuncSetAttribute(gemm_hmma_kernel,
                         cudaFuncAttributeMaxDynamicSharedMemorySize, GSMEM);

    // weight/input splits
    convsplit_kernel<<<(VV * HH / 4 + 255) / 256, 256>>>(we, weh, wel, VV * HH / 4);
    convsplit_kernel<<<(2 * 4 * HH * HH / 4 + 255) / 256, 256>>>(Wih, wihh, wihl,
                                                                 2 * 4 * HH * HH / 4);
    embed_kernel<<<dim3(TT, BB), 256>>>(ids, we, pe, fh, fl);

    // layer0 input gates
    gemm_hmma_kernel<<<dim3(4 * HH / 128, TT * BB / 128), 256, GSMEM>>>(
        fh, fl, wihh, wihl, bih, bhh, gates, 4 * HH);
    reset_counters_kernel<<<1, NCTR * 32>>>(counters);
    lstm_layer_kernel<<<NBLK, 256, lsmem>>>(gates, Whh, h0, counters);

    // layer1
    convsplit_kernel<<<(TT * BB * HH / 4 + 255) / 256, 256>>>(h0, h0h, h0l, TT * BB * HH / 4);
    gemm_hmma_kernel<<<dim3(4 * HH / 128, TT * BB / 128), 256, GSMEM>>>(
        h0h, h0l, wihh + (size_t)4 * HH * HH, wihl + (size_t)4 * HH * HH,
        bih + 4 * HH, bhh + 4 * HH, gates, 4 * HH);
    reset_counters_kernel<<<1, NCTR * 32>>>(counters);
    lstm_layer_kernel<<<NBLK, 256, lsmem>>>(gates, Whh + (size_t)4 * HH * HH, h1, counters);

    // layernorm + head
    layernorm_kernel<<<dim3(TT, BB), 256>>>(h1, lnw, lnb, xnh, xnl);
    gemm_hmma_kernel<<<dim3(VV / 128, TT * BB / 128), 256, GSMEM>>>(
        xnh, xnl, weh, wel, nullptr, nullptr, out, VV);
}

// round 13
// speedup vs baseline: 1.5428x; 1.4938x over previous
#include <cuda_runtime.h>
#include <cuda_bf16.h>
#include <cstdint>
#include <math.h>

#define TT 1024
#define BB 4
#define HH 1024
#define VV 32000
#define NBLK 128
#define UPB 8

typedef unsigned long long ull;

// ======================= helpers =======================
__device__ __forceinline__ uint32_t smem_to_u32(const void* p) {
    uint32_t a;
    asm("{ .reg .u64 t; cvta.to.shared.u64 t, %1; cvt.u32.u64 %0, t; }" : "=r"(a) : "l"(p));
    return a;
}
__device__ __forceinline__ void cp16(uint32_t dst, const void* src) {
    asm volatile("cp.async.cg.shared.global [%0], [%1], 16;" :: "r"(dst), "l"(src) : "memory");
}
#define CP_COMMIT() asm volatile("cp.async.commit_group;" ::: "memory")
#define CP_WAIT(n)  asm volatile("cp.async.wait_group %0;" :: "n"(n) : "memory")

#define LDSM_X4(r0, r1, r2, r3, addr) \
    asm volatile("ldmatrix.sync.aligned.m8n8.x4.shared.b16 {%0,%1,%2,%3}, [%4];" \
        : "=r"(r0), "=r"(r1), "=r"(r2), "=r"(r3) : "r"(addr))
#define MMA16816(c0, c1, c2, c3, a0, a1, a2, a3, b0, b1) \
    asm volatile("mma.sync.aligned.m16n8k16.row.col.f32.bf16.bf16.f32 " \
        "{%0,%1,%2,%3}, {%4,%5,%6,%7}, {%8,%9}, {%0,%1,%2,%3};" \
        : "+f"(c0), "+f"(c1), "+f"(c2), "+f"(c3) \
        : "r"(a0), "r"(a1), "r"(a2), "r"(a3), "r"(b0), "r"(b1))

// packed dual-fp32 FMA (FFMA2): acc.xy += w.xy * h.xy
#define FMA2(acc, w, h) \
    asm("fma.rn.f32x2 %0, %1, %2, %0;" : "+l"(acc) : "l"(w), "l"(h))
__device__ __forceinline__ float f2sum(ull v) {
    return __uint_as_float((unsigned)v) + __uint_as_float((unsigned)(v >> 32));
}

// ======================= scratch =======================
__device__ __nv_bfloat16 g_weh[(size_t)VV * HH];
__device__ __nv_bfloat16 g_wel[(size_t)VV * HH];
__device__ __nv_bfloat16 g_wihh[(size_t)2 * 4 * HH * HH];
__device__ __nv_bfloat16 g_wihl[(size_t)2 * 4 * HH * HH];
__device__ __nv_bfloat16 g_fh[(size_t)TT * BB * HH];
__device__ __nv_bfloat16 g_fl[(size_t)TT * BB * HH];
__device__ __nv_bfloat16 g_h0h[(size_t)TT * BB * HH];
__device__ __nv_bfloat16 g_h0l[(size_t)TT * BB * HH];
__device__ __nv_bfloat16 g_xnh[(size_t)TT * BB * HH];
__device__ __nv_bfloat16 g_xnl[(size_t)TT * BB * HH];
__device__ float g_gates[(size_t)TT * BB * 4 * HH];
__device__ float g_h0[(size_t)TT * BB * HH];
__device__ float g_h1[(size_t)TT * BB * HH];
__device__ unsigned g_counter;

__device__ __forceinline__ void split_bf16(float v, __nv_bfloat16& hi, __nv_bfloat16& lo) {
    __nv_bfloat16 h = __float2bfloat16(v);
    hi = h;
    lo = __float2bfloat16(v - __bfloat162float(h));
}

// ======================= fp32 -> bf16 hi/lo split =======================
__global__ __launch_bounds__(256) void convsplit_kernel(
    const float* __restrict__ in, __nv_bfloat16* __restrict__ hi,
    __nv_bfloat16* __restrict__ lo, int n4)
{
    int i = blockIdx.x * blockDim.x + threadIdx.x;
    if (i >= n4) return;
    float4 v = ((const float4*)in)[i];
    __nv_bfloat16 h0, h1, h2, h3, l0, l1, l2, l3;
    split_bf16(v.x, h0, l0); split_bf16(v.y, h1, l1);
    split_bf16(v.z, h2, l2); split_bf16(v.w, h3, l3);
    ((__nv_bfloat162*)hi)[i * 2 + 0] = __nv_bfloat162(h0, h1);
    ((__nv_bfloat162*)hi)[i * 2 + 1] = __nv_bfloat162(h2, h3);
    ((__nv_bfloat162*)lo)[i * 2 + 0] = __nv_bfloat162(l0, l1);
    ((__nv_bfloat162*)lo)[i * 2 + 1] = __nv_bfloat162(l2, l3);
}

// ======================= embedding -> bf16 split, time-major =======================
__global__ __launch_bounds__(256) void embed_kernel(
    const int* __restrict__ ids, const float* __restrict__ we,
    const float* __restrict__ pe, __nv_bfloat16* __restrict__ oh,
    __nv_bfloat16* __restrict__ ol)
{
    int t = blockIdx.x, b = blockIdx.y;
    int id = ids[b * TT + t];
    const float4* w = (const float4*)(we + (size_t)id * HH);
    const float4* p = (const float4*)(pe + (size_t)t * HH);
    size_t row = ((size_t)t * BB + b) * HH;
    for (int i = threadIdx.x; i < HH / 4; i += blockDim.x) {
        float4 a = w[i], c = p[i];
        float4 v = make_float4(a.x + c.x, a.y + c.y, a.z + c.z, a.w + c.w);
        __nv_bfloat16 h0, h1, h2, h3, l0, l1, l2, l3;
        split_bf16(v.x, h0, l0); split_bf16(v.y, h1, l1);
        split_bf16(v.z, h2, l2); split_bf16(v.w, h3, l3);
        ((__nv_bfloat162*)(oh + row))[i * 2 + 0] = __nv_bfloat162(h0, h1);
        ((__nv_bfloat162*)(oh + row))[i * 2 + 1] = __nv_bfloat162(h2, h3);
        ((__nv_bfloat162*)(ol + row))[i * 2 + 0] = __nv_bfloat162(l0, l1);
        ((__nv_bfloat162*)(ol + row))[i * 2 + 1] = __nv_bfloat162(l2, l3);
    }
}

// ======================= HMMA split-bf16 NT GEMM (known-good, unchanged) =======================
#define TSTRIDE 40
#define TILE_E  (128 * TSTRIDE)
#define TILE_BYTES (TILE_E * 2)            // 10240
#define BUF_BYTES (4 * TILE_BYTES)         // 40960
#define GSMEM (2 * BUF_BYTES)              // 81920

__global__ __launch_bounds__(256, 2) void gemm_hmma_kernel(
    const __nv_bfloat16* __restrict__ Ah, const __nv_bfloat16* __restrict__ Al,
    const __nv_bfloat16* __restrict__ Bh, const __nv_bfloat16* __restrict__ Bl,
    const float* __restrict__ bias0, const float* __restrict__ bias1,
    float* __restrict__ C, int N)
{
    extern __shared__ __nv_bfloat16 sm[];
    const uint32_t sbase = smem_to_u32(sm);
    const int tid = threadIdx.x;
    const int lane = tid & 31;
    const int wid = tid >> 5;
    const int wm = wid & 3;
    const int wn = wid >> 2;
    const int bn = blockIdx.x << 7;
    const int bm = blockIdx.y << 7;

    float acc[2][8][4];
#pragma unroll
    for (int mt = 0; mt < 2; ++mt)
#pragma unroll
        for (int nt = 0; nt < 8; ++nt)
#pragma unroll
            for (int q = 0; q < 4; ++q) acc[mt][nt][q] = 0.f;

    const __nv_bfloat16* srcs[4] = { Ah, Al, Bh, Bl };
    const int rb[4] = { bm, bm, bn, bn };

    auto load_chunk = [&](int c) {
        uint32_t buf = sbase + (c & 1) * BUF_BYTES;
#pragma unroll
        for (int tsel = 0; tsel < 4; ++tsel) {
            uint32_t dst = buf + tsel * TILE_BYTES;
            const __nv_bfloat16* base = srcs[tsel];
#pragma unroll
            for (int i = 0; i < 2; ++i) {
                int s = tid + (i << 8);
                int row = s >> 2, k8 = s & 3;
                cp16(dst + row * (TSTRIDE * 2) + k8 * 16,
                     base + (size_t)(rb[tsel] + row) * 1024 + c * 32 + k8 * 8);
            }
        }
        CP_COMMIT();
    };

    load_chunk(0);

    for (int c = 0; c < 32; ++c) {
        if (c < 31) { load_chunk(c + 1); CP_WAIT(1); }
        else        { CP_WAIT(0); }
        __syncthreads();

        uint32_t buf = sbase + (c & 1) * BUF_BYTES;
        const int a_r = (lane & 15);
        const int a_k = (lane >> 4) << 3;
        const int b_n = ((lane >> 4) << 3) + (lane & 7);
        const int b_k = ((lane >> 3) & 1) << 3;

#pragma unroll
        for (int ks = 0; ks < 2; ++ks) {
            const int kbase = ks << 4;
            uint32_t ah[2][4], al[2][4], bh[16], bl[16];
#pragma unroll
            for (int mt = 0; mt < 2; ++mt) {
                int row = wm * 32 + mt * 16 + a_r;
                uint32_t addr = buf + (row * TSTRIDE + kbase + a_k) * 2;
                LDSM_X4(ah[mt][0], ah[mt][1], ah[mt][2], ah[mt][3], addr);
                LDSM_X4(al[mt][0], al[mt][1], al[mt][2], al[mt][3], addr + TILE_BYTES);
            }
#pragma unroll
            for (int np = 0; np < 4; ++np) {
                int nrow = wn * 64 + np * 16 + b_n;
                uint32_t addr = buf + 2 * TILE_BYTES + (nrow * TSTRIDE + kbase + b_k) * 2;
                LDSM_X4(bh[np * 4 + 0], bh[np * 4 + 1], bh[np * 4 + 2], bh[np * 4 + 3], addr);
                LDSM_X4(bl[np * 4 + 0], bl[np * 4 + 1], bl[np * 4 + 2], bl[np * 4 + 3],
                        addr + TILE_BYTES);
            }
#pragma unroll
            for (int mt = 0; mt < 2; ++mt)
#pragma unroll
                for (int nt = 0; nt < 8; ++nt) {
                    float* cc = acc[mt][nt];
                    MMA16816(cc[0], cc[1], cc[2], cc[3],
                             ah[mt][0], ah[mt][1], ah[mt][2], ah[mt][3],
                             bh[nt * 2], bh[nt * 2 + 1]);
                    MMA16816(cc[0], cc[1], cc[2], cc[3],
                             al[mt][0], al[mt][1], al[mt][2], al[mt][3],
                             bh[nt * 2], bh[nt * 2 + 1]);
                    MMA16816(cc[0], cc[1], cc[2], cc[3],
                             ah[mt][0], ah[mt][1], ah[mt][2], ah[mt][3],
                             bl[nt * 2], bl[nt * 2 + 1]);
                }
        }
        __syncthreads();
    }

#pragma unroll
    for (int mt = 0; mt < 2; ++mt) {
        int row0 = bm + wm * 32 + mt * 16 + (lane >> 2);
#pragma unroll
        for (int nt = 0; nt < 8; ++nt) {
            int col = bn + wn * 64 + nt * 8 + ((lane & 3) << 1);
            float b0v = 0.f, b1v = 0.f;
            if (bias0) {
                b0v = bias0[col] + bias1[col];
                b1v = bias0[col + 1] + bias1[col + 1];
            }
            float* c0 = C + (size_t)row0 * N + col;
            float* c1 = C + (size_t)(row0 + 8) * N + col;
            *(float2*)c0 = make_float2(acc[mt][nt][0] + b0v, acc[mt][nt][1] + b1v);
            *(float2*)c1 = make_float2(acc[mt][nt][2] + b0v, acc[mt][nt][3] + b1v);
        }
    }
}

// ======================= persistent LSTM recurrence =======================
// R9 dots + R9 single-counter barrier, with:
//  - reduce+cell merged into warp 0 (cell state in registers, no gsm[])
//  - early release: h-writers are all warp 0 -> __syncwarp orders stores, release
//    fires before warps 1-7 drain (they run ahead to the next round's entry sync)
//  - fast-math cell (MUFU __expf)
__device__ __forceinline__ float sigm_f(float x) { return 1.f / (1.f + __expf(-x)); }
__device__ __forceinline__ float tanh_f(float x) { return 2.f / (1.f + __expf(-2.f * x)) - 1.f; }

__global__ __launch_bounds__(256) void lstm_layer_kernel(
    const float* __restrict__ gates_in, const float* __restrict__ Whh,
    float* __restrict__ hout, unsigned* counter)
{
    extern __shared__ float smf[];
    float* Wsh   = smf;                      // [32][1028]
    float* hsh   = Wsh + 32 * 1028;          // [4][1024]
    float* part  = hsh + 4 * 1024;           // [8][32][4]
    float* ginsh = part + 8 * 32 * 4;        // [128]

    const int tid = threadIdx.x;
    const int blk = blockIdx.x;
    const int u0 = blk * UPB;

#pragma unroll
    for (int r = 0; r < 32; ++r) {
        int g = r >> 3, u = r & 7;
        const float* src = Whh + (size_t)(g * HH + u0 + u) * HH;
        *(float4*)(Wsh + r * 1028 + tid * 4) = *(const float4*)(src + tid * 4);
    }
    for (int i = tid * 4; i < BB * HH; i += 1024)
        *(float4*)(hsh + i) = make_float4(0.f, 0.f, 0.f, 0.f);
    __syncthreads();

    const int j  = tid & 31;
    const int ks = tid >> 5;
    const int jj = tid >> 2, bb = tid & 3;
    const int gg = jj >> 3, uu = jj & 7;
    const float* gptr = gates_in + (size_t)bb * (4 * HH) + gg * HH + u0 + uu;
    float cstate = 0.f;      // valid for tid < 32 (cell lane owns (u=tid>>2, b=tid&3))

    for (int t = 0; t < TT; ++t) {
        // prefetch this step's gate input (latency hides under the barrier wait)
        float gin = 0.f;
        if (tid < 128) gin = __ldg(gptr + (size_t)t * BB * 4 * HH);

        if (t > 0) {
            if (tid == 0) {
                unsigned tgt = (unsigned)NBLK * (unsigned)t;
                unsigned v;
                do {
                    asm volatile("ld.acquire.gpu.global.u32 %0, [%1];"
                                 : "=r"(v) : "l"(counter));
                } while (v < tgt);
            }
            __syncthreads();                      // entry sync: joins warp0 after cell(t-1)
            if (tid < 128) ginsh[tid] = gin;      // safe: warp0 past cell(t-1) reads
            const float* hp = hout + (size_t)(t - 1) * BB * HH;
            for (int i = tid * 4; i < BB * HH; i += 1024)
                *(float4*)(hsh + i) = __ldcg((const float4*)(hp + i));
            __syncthreads();
        } else {
            if (tid < 128) ginsh[tid] = gin;
            __syncthreads();
        }

        // packed f32x2 partial dots: acc.xy[b] += W[j][k,k+1] * h[b][k,k+1]
        {
            const float* wr = Wsh + j * 1028 + (ks << 7);
            const float* hb = hsh + (ks << 7);
            ull a0 = 0ull, a1 = 0ull, a2 = 0ull, a3 = 0ull;
#pragma unroll 8
            for (int k = 0; k < 128; k += 4) {
                ulonglong2 wv = *(const ulonglong2*)(wr + k);
                ulonglong2 x0 = *(const ulonglong2*)(hb + k);
                ulonglong2 x1 = *(const ulonglong2*)(hb + 1024 + k);
                ulonglong2 x2 = *(const ulonglong2*)(hb + 2048 + k);
                ulonglong2 x3 = *(const ulonglong2*)(hb + 3072 + k);
                FMA2(a0, wv.x, x0.x); FMA2(a0, wv.y, x0.y);
                FMA2(a1, wv.x, x1.x); FMA2(a1, wv.y, x1.y);
                FMA2(a2, wv.x, x2.x); FMA2(a2, wv.y, x2.y);
                FMA2(a3, wv.x, x3.x); FMA2(a3, wv.y, x3.y);
            }
            *(float4*)(part + ((ks << 5) + j) * 4) =
                make_float4(f2sum(a0), f2sum(a1), f2sum(a2), f2sum(a3));
        }
        __syncthreads();     // parts ready (warps 1-7 run ahead to next entry sync)

        // warp 0: merged reduce + cell + store + early release
        if (tid < 32) {
            int u = tid >> 2, b = tid & 3;
            float s[4];
#pragma unroll
            for (int g = 0; g < 4; ++g) {
                int row = g * 8 + u;
                float acc = ginsh[(g << 5) + (u << 2) + b];
#pragma unroll
                for (int q = 0; q < 8; ++q)
                    acc += part[((q << 5) + row) * 4 + b];
                s[g] = acc;
            }
            float cn = sigm_f(s[1]) * cstate + sigm_f(s[0]) * tanh_f(s[2]);
            float hn = sigm_f(s[3]) * tanh_f(cn);
            cstate = cn;
            hout[((size_t)t * BB + b) * HH + u0 + u] = hn;
            __syncwarp();    // all 32 h-stores ordered before the release below
            if (tid == 0) {
                asm volatile("red.release.gpu.global.add.u32 [%0], %1;"
                             :: "l"(counter), "r"(1u) : "memory");
            }
        }
    }
}

__global__ void reset_counter_kernel(unsigned* c)
{
    if (threadIdx.x == 0) *c = 0u;
}

// ======================= LayerNorm -> bf16 split, batch-major =======================
__global__ __launch_bounds__(256) void layernorm_kernel(
    const float* __restrict__ in, const float* __restrict__ w,
    const float* __restrict__ bv, __nv_bfloat16* __restrict__ oh,
    __nv_bfloat16* __restrict__ ol)
{
    int t = blockIdx.x, b = blockIdx.y;
    const float* x = in + ((size_t)t * BB + b) * HH;
    size_t orow = ((size_t)b * TT + t) * HH;
    __shared__ float row[HH];
    __shared__ float red[8];
    __shared__ float stat[2];
    int tid = threadIdx.x;

    float s = 0.f;
    for (int i = tid; i < HH; i += 256) { float v = x[i]; row[i] = v; s += v; }
#pragma unroll
    for (int off = 16; off; off >>= 1) s += __shfl_xor_sync(0xffffffffu, s, off);
    if ((tid & 31) == 0) red[tid >> 5] = s;
    __syncthreads();
    if (tid == 0) {
        float tot = 0.f;
        for (int i = 0; i < 8; ++i) tot += red[i];
        stat[0] = tot * (1.f / HH);
    }
    __syncthreads();
    float mu = stat[0];
    float v2 = 0.f;
    for (int i = tid; i < HH; i += 256) { float d = row[i] - mu; v2 += d * d; }
#pragma unroll
    for (int off = 16; off; off >>= 1) v2 += __shfl_xor_sync(0xffffffffu, v2, off);
    __syncthreads();
    if ((tid & 31) == 0) red[tid >> 5] = v2;
    __syncthreads();
    if (tid == 0) {
        float tot = 0.f;
        for (int i = 0; i < 8; ++i) tot += red[i];
        stat[1] = rsqrtf(tot * (1.f / HH) + 1e-5f);
    }
    __syncthreads();
    float inv = stat[1];
    for (int i = tid; i < HH; i += 256) {
        float v = (row[i] - mu) * inv * w[i] + bv[i];
        __nv_bfloat16 hi, lo;
        split_bf16(v, hi, lo);
        oh[orow + i] = hi;
        ol[orow + i] = lo;
    }
}

// ======================= launch =======================
extern "C" void kernel_launch(void* const* d_in, const int* in_sizes, int n_in,
                              void* d_out, int out_size)
{
    (void)in_sizes; (void)n_in; (void)out_size;
    const int*   ids = (const int*)d_in[0];
    const float* we  = (const float*)d_in[1];
    const float* pe  = (const float*)d_in[2];
    const float* Wih = (const float*)d_in[3];
    const float* Whh = (const float*)d_in[4];
    const float* bih = (const float*)d_in[5];
    const float* bhh = (const float*)d_in[6];
    const float* lnw = (const float*)d_in[7];
    const float* lnb = (const float*)d_in[8];
    float* out = (float*)d_out;

    __nv_bfloat16 *weh, *wel, *wihh, *wihl, *fh, *fl, *h0h, *h0l, *xnh, *xnl;
    float *gates, *h0, *h1; unsigned* counter;
    cudaGetSymbolAddress((void**)&weh,  g_weh);
    cudaGetSymbolAddress((void**)&wel,  g_wel);
    cudaGetSymbolAddress((void**)&wihh, g_wihh);
    cudaGetSymbolAddress((void**)&wihl, g_wihl);
    cudaGetSymbolAddress((void**)&fh,   g_fh);
    cudaGetSymbolAddress((void**)&fl,   g_fl);
    cudaGetSymbolAddress((void**)&h0h,  g_h0h);
    cudaGetSymbolAddress((void**)&h0l,  g_h0l);
    cudaGetSymbolAddress((void**)&xnh,  g_xnh);
    cudaGetSymbolAddress((void**)&xnl,  g_xnl);
    cudaGetSymbolAddress((void**)&gates, g_gates);
    cudaGetSymbolAddress((void**)&h0,    g_h0);
    cudaGetSymbolAddress((void**)&h1,    g_h1);
    cudaGetSymbolAddress((void**)&counter, g_counter);

    size_t lsmem = (size_t)(32 * 1028 + 4 * 1024 + 8 * 32 * 4 + 128) * sizeof(float);
    cudaFuncSetAttribute(lstm_layer_kernel,
                         cudaFuncAttributeMaxDynamicSharedMemorySize, (int)lsmem);
    cudaFuncSetAttribute(gemm_hmma_kernel,
                         cudaFuncAttributeMaxDynamicSharedMemorySize, GSMEM);

    // weight/input splits
    convsplit_kernel<<<(VV * HH / 4 + 255) / 256, 256>>>(we, weh, wel, VV * HH / 4);
    convsplit_kernel<<<(2 * 4 * HH * HH / 4 + 255) / 256, 256>>>(Wih, wihh, wihl,
                                                                 2 * 4 * HH * HH / 4);
    embed_kernel<<<dim3(TT, BB), 256>>>(ids, we, pe, fh, fl);

    // layer0 input gates
    gemm_hmma_kernel<<<dim3(4 * HH / 128, TT * BB / 128), 256, GSMEM>>>(
        fh, fl, wihh, wihl, bih, bhh, gates, 4 * HH);
    reset_counter_kernel<<<1, 32>>>(counter);
    lstm_layer_kernel<<<NBLK, 256, lsmem>>>(gates, Whh, h0, counter);

    // layer1
    convsplit_kernel<<<(TT * BB * HH / 4 + 255) / 256, 256>>>(h0, h0h, h0l, TT * BB * HH / 4);
    gemm_hmma_kernel<<<dim3(4 * HH / 128, TT * BB / 128), 256, GSMEM>>>(
        h0h, h0l, wihh + (size_t)4 * HH * HH, wihl + (size_t)4 * HH * HH,
        bih + 4 * HH, bhh + 4 * HH, gates, 4 * HH);
    reset_counter_kernel<<<1, 32>>>(counter);
    lstm_layer_kernel<<<NBLK, 256, lsmem>>>(gates, Whh + (size_t)4 * HH * HH, h1, counter);

    // layernorm + head
    layernorm_kernel<<<dim3(TT, BB), 256>>>(h1, lnw, lnb, xnh, xnl);
    gemm_hmma_kernel<<<dim3(VV / 128, TT * BB / 128), 256, GSMEM>>>(
        xnh, xnl, weh, wel, nullptr, nullptr, out, VV);
}

// round 14
// speedup vs baseline: 1.6692x; 1.0819x over previous
#include <cuda_runtime.h>
#include <cuda_bf16.h>
#include <cstdint>
#include <math.h>

#define TT 1024
#define BB 4
#define HH 1024
#define VV 32000
#define NBLK 128
#define UPB 8

typedef unsigned long long ull;

// ======================= helpers =======================
__device__ __forceinline__ uint32_t smem_to_u32(const void* p) {
    uint32_t a;
    asm("{ .reg .u64 t; cvta.to.shared.u64 t, %1; cvt.u32.u64 %0, t; }" : "=r"(a) : "l"(p));
    return a;
}
__device__ __forceinline__ void cp16(uint32_t dst, const void* src) {
    asm volatile("cp.async.cg.shared.global [%0], [%1], 16;" :: "r"(dst), "l"(src) : "memory");
}
#define CP_COMMIT() asm volatile("cp.async.commit_group;" ::: "memory")
#define CP_WAIT(n)  asm volatile("cp.async.wait_group %0;" :: "n"(n) : "memory")

#define LDSM_X4(r0, r1, r2, r3, addr) \
    asm volatile("ldmatrix.sync.aligned.m8n8.x4.shared.b16 {%0,%1,%2,%3}, [%4];" \
        : "=r"(r0), "=r"(r1), "=r"(r2), "=r"(r3) : "r"(addr))
#define MMA16816(c0, c1, c2, c3, a0, a1, a2, a3, b0, b1) \
    asm volatile("mma.sync.aligned.m16n8k16.row.col.f32.bf16.bf16.f32 " \
        "{%0,%1,%2,%3}, {%4,%5,%6,%7}, {%8,%9}, {%0,%1,%2,%3};" \
        : "+f"(c0), "+f"(c1), "+f"(c2), "+f"(c3) \
        : "r"(a0), "r"(a1), "r"(a2), "r"(a3), "r"(b0), "r"(b1))

// packed dual-fp32 FMA (FFMA2): acc.xy += w.xy * h.xy
#define FMA2(acc, w, h) \
    asm("fma.rn.f32x2 %0, %1, %2, %0;" : "+l"(acc) : "l"(w), "l"(h))
__device__ __forceinline__ float f2sum(ull v) {
    return __uint_as_float((unsigned)v) + __uint_as_float((unsigned)(v >> 32));
}

// ======================= scratch =======================
__device__ __nv_bfloat16 g_weh[(size_t)VV * HH];
__device__ __nv_bfloat16 g_wel[(size_t)VV * HH];
__device__ __nv_bfloat16 g_wihh[(size_t)2 * 4 * HH * HH];
__device__ __nv_bfloat16 g_wihl[(size_t)2 * 4 * HH * HH];
__device__ __nv_bfloat16 g_fh[(size_t)TT * BB * HH];
__device__ __nv_bfloat16 g_fl[(size_t)TT * BB * HH];
__device__ __nv_bfloat16 g_h0h[(size_t)TT * BB * HH];
__device__ __nv_bfloat16 g_h0l[(size_t)TT * BB * HH];
__device__ __nv_bfloat16 g_xnh[(size_t)TT * BB * HH];
__device__ __nv_bfloat16 g_xnl[(size_t)TT * BB * HH];
__device__ float g_gates[(size_t)TT * BB * 4 * HH];
__device__ float g_h0[(size_t)TT * BB * HH];
__device__ float g_h1[(size_t)TT * BB * HH];
__device__ unsigned g_counter;

__device__ __forceinline__ void split_bf16(float v, __nv_bfloat16& hi, __nv_bfloat16& lo) {
    __nv_bfloat16 h = __float2bfloat16(v);
    hi = h;
    lo = __float2bfloat16(v - __bfloat162float(h));
}

// ======================= fp32 -> bf16 hi/lo split =======================
__global__ __launch_bounds__(256) void convsplit_kernel(
    const float* __restrict__ in, __nv_bfloat16* __restrict__ hi,
    __nv_bfloat16* __restrict__ lo, int n4)
{
    int i = blockIdx.x * blockDim.x + threadIdx.x;
    if (i >= n4) return;
    float4 v = ((const float4*)in)[i];
    __nv_bfloat16 h0, h1, h2, h3, l0, l1, l2, l3;
    split_bf16(v.x, h0, l0); split_bf16(v.y, h1, l1);
    split_bf16(v.z, h2, l2); split_bf16(v.w, h3, l3);
    ((__nv_bfloat162*)hi)[i * 2 + 0] = __nv_bfloat162(h0, h1);
    ((__nv_bfloat162*)hi)[i * 2 + 1] = __nv_bfloat162(h2, h3);
    ((__nv_bfloat162*)lo)[i * 2 + 0] = __nv_bfloat162(l0, l1);
    ((__nv_bfloat162*)lo)[i * 2 + 1] = __nv_bfloat162(l2, l3);
}

// ======================= embedding -> bf16 split, time-major =======================
__global__ __launch_bounds__(256) void embed_kernel(
    const int* __restrict__ ids, const float* __restrict__ we,
    const float* __restrict__ pe, __nv_bfloat16* __restrict__ oh,
    __nv_bfloat16* __restrict__ ol)
{
    int t = blockIdx.x, b = blockIdx.y;
    int id = ids[b * TT + t];
    const float4* w = (const float4*)(we + (size_t)id * HH);
    const float4* p = (const float4*)(pe + (size_t)t * HH);
    size_t row = ((size_t)t * BB + b) * HH;
    for (int i = threadIdx.x; i < HH / 4; i += blockDim.x) {
        float4 a = w[i], c = p[i];
        float4 v = make_float4(a.x + c.x, a.y + c.y, a.z + c.z, a.w + c.w);
        __nv_bfloat16 h0, h1, h2, h3, l0, l1, l2, l3;
        split_bf16(v.x, h0, l0); split_bf16(v.y, h1, l1);
        split_bf16(v.z, h2, l2); split_bf16(v.w, h3, l3);
        ((__nv_bfloat162*)(oh + row))[i * 2 + 0] = __nv_bfloat162(h0, h1);
        ((__nv_bfloat162*)(oh + row))[i * 2 + 1] = __nv_bfloat162(h2, h3);
        ((__nv_bfloat162*)(ol + row))[i * 2 + 0] = __nv_bfloat162(l0, l1);
        ((__nv_bfloat162*)(ol + row))[i * 2 + 1] = __nv_bfloat162(l2, l3);
    }
}

// ======================= HMMA split-bf16 NT GEMM (known-good, unchanged) =======================
#define TSTRIDE 40
#define TILE_E  (128 * TSTRIDE)
#define TILE_BYTES (TILE_E * 2)            // 10240
#define BUF_BYTES (4 * TILE_BYTES)         // 40960
#define GSMEM (2 * BUF_BYTES)              // 81920

__global__ __launch_bounds__(256, 2) void gemm_hmma_kernel(
    const __nv_bfloat16* __restrict__ Ah, const __nv_bfloat16* __restrict__ Al,
    const __nv_bfloat16* __restrict__ Bh, const __nv_bfloat16* __restrict__ Bl,
    const float* __restrict__ bias0, const float* __restrict__ bias1,
    float* __restrict__ C, int N)
{
    extern __shared__ __nv_bfloat16 sm[];
    const uint32_t sbase = smem_to_u32(sm);
    const int tid = threadIdx.x;
    const int lane = tid & 31;
    const int wid = tid >> 5;
    const int wm = wid & 3;
    const int wn = wid >> 2;
    const int bn = blockIdx.x << 7;
    const int bm = blockIdx.y << 7;

    float acc[2][8][4];
#pragma unroll
    for (int mt = 0; mt < 2; ++mt)
#pragma unroll
        for (int nt = 0; nt < 8; ++nt)
#pragma unroll
            for (int q = 0; q < 4; ++q) acc[mt][nt][q] = 0.f;

    const __nv_bfloat16* srcs[4] = { Ah, Al, Bh, Bl };
    const int rb[4] = { bm, bm, bn, bn };

    auto load_chunk = [&](int c) {
        uint32_t buf = sbase + (c & 1) * BUF_BYTES;
#pragma unroll
        for (int tsel = 0; tsel < 4; ++tsel) {
            uint32_t dst = buf + tsel * TILE_BYTES;
            const __nv_bfloat16* base = srcs[tsel];
#pragma unroll
            for (int i = 0; i < 2; ++i) {
                int s = tid + (i << 8);
                int row = s >> 2, k8 = s & 3;
                cp16(dst + row * (TSTRIDE * 2) + k8 * 16,
                     base + (size_t)(rb[tsel] + row) * 1024 + c * 32 + k8 * 8);
            }
        }
        CP_COMMIT();
    };

    load_chunk(0);

    for (int c = 0; c < 32; ++c) {
        if (c < 31) { load_chunk(c + 1); CP_WAIT(1); }
        else        { CP_WAIT(0); }
        __syncthreads();

        uint32_t buf = sbase + (c & 1) * BUF_BYTES;
        const int a_r = (lane & 15);
        const int a_k = (lane >> 4) << 3;
        const int b_n = ((lane >> 4) << 3) + (lane & 7);
        const int b_k = ((lane >> 3) & 1) << 3;

#pragma unroll
        for (int ks = 0; ks < 2; ++ks) {
            const int kbase = ks << 4;
            uint32_t ah[2][4], al[2][4], bh[16], bl[16];
#pragma unroll
            for (int mt = 0; mt < 2; ++mt) {
                int row = wm * 32 + mt * 16 + a_r;
                uint32_t addr = buf + (row * TSTRIDE + kbase + a_k) * 2;
                LDSM_X4(ah[mt][0], ah[mt][1], ah[mt][2], ah[mt][3], addr);
                LDSM_X4(al[mt][0], al[mt][1], al[mt][2], al[mt][3], addr + TILE_BYTES);
            }
#pragma unroll
            for (int np = 0; np < 4; ++np) {
                int nrow = wn * 64 + np * 16 + b_n;
                uint32_t addr = buf + 2 * TILE_BYTES + (nrow * TSTRIDE + kbase + b_k) * 2;
                LDSM_X4(bh[np * 4 + 0], bh[np * 4 + 1], bh[np * 4 + 2], bh[np * 4 + 3], addr);
                LDSM_X4(bl[np * 4 + 0], bl[np * 4 + 1], bl[np * 4 + 2], bl[np * 4 + 3],
                        addr + TILE_BYTES);
            }
#pragma unroll
            for (int mt = 0; mt < 2; ++mt)
#pragma unroll
                for (int nt = 0; nt < 8; ++nt) {
                    float* cc = acc[mt][nt];
                    MMA16816(cc[0], cc[1], cc[2], cc[3],
                             ah[mt][0], ah[mt][1], ah[mt][2], ah[mt][3],
                             bh[nt * 2], bh[nt * 2 + 1]);
                    MMA16816(cc[0], cc[1], cc[2], cc[3],
                             al[mt][0], al[mt][1], al[mt][2], al[mt][3],
                             bh[nt * 2], bh[nt * 2 + 1]);
                    MMA16816(cc[0], cc[1], cc[2], cc[3],
                             ah[mt][0], ah[mt][1], ah[mt][2], ah[mt][3],
                             bl[nt * 2], bl[nt * 2 + 1]);
                }
        }
        __syncthreads();
    }

#pragma unroll
    for (int mt = 0; mt < 2; ++mt) {
        int row0 = bm + wm * 32 + mt * 16 + (lane >> 2);
#pragma unroll
        for (int nt = 0; nt < 8; ++nt) {
            int col = bn + wn * 64 + nt * 8 + ((lane & 3) << 1);
            float b0v = 0.f, b1v = 0.f;
            if (bias0) {
                b0v = bias0[col] + bias1[col];
                b1v = bias0[col + 1] + bias1[col + 1];
            }
            float* c0 = C + (size_t)row0 * N + col;
            float* c1 = C + (size_t)(row0 + 8) * N + col;
            *(float2*)c0 = make_float2(acc[mt][nt][0] + b0v, acc[mt][nt][1] + b1v);
            *(float2*)c1 = make_float2(acc[mt][nt][2] + b0v, acc[mt][nt][3] + b1v);
        }
    }
}

// ======================= persistent LSTM recurrence =======================
// R13 structure (merged warp-0 reduce+cell, early release, fast-math) with
// W moved from SMEM into registers: thread (ks=tid>>5, j=tid&31) holds
// W row (g=j>>3, u=j&7), words [128ks, 128ks+128) as ull wreg[64].
// Removes 32 LDS.128/lane/step (~1024 crossbar cyc + 32 issue slots).
__device__ __forceinline__ float sigm_f(float x) { return 1.f / (1.f + __expf(-x)); }
__device__ __forceinline__ float tanh_f(float x) { return 2.f / (1.f + __expf(-2.f * x)) - 1.f; }

__global__ __launch_bounds__(256, 1) void lstm_layer_kernel(
    const float* __restrict__ gates_in, const float* __restrict__ Whh,
    float* __restrict__ hout, unsigned* counter)
{
    extern __shared__ float smf[];
    float* hsh   = smf;                      // [4][1024]
    float* part  = hsh + 4 * 1024;           // [8][32][4]
    float* ginsh = part + 8 * 32 * 4;        // [128]

    const int tid = threadIdx.x;
    const int blk = blockIdx.x;
    const int u0 = blk * UPB;

    const int j  = tid & 31;
    const int ks = tid >> 5;

    // one-time: W slice into registers (constant-indexed, fully unrolled)
    ull wreg[64];
    {
        const float* src = Whh + (size_t)((j >> 3) * HH + u0 + (j & 7)) * HH + (ks << 7);
#pragma unroll
        for (int i = 0; i < 64; ++i)
            wreg[i] = *(const ull*)(src + i * 2);
    }

    for (int i = tid * 4; i < BB * HH; i += 1024)
        *(float4*)(hsh + i) = make_float4(0.f, 0.f, 0.f, 0.f);
    __syncthreads();

    const int jj = tid >> 2, bb = tid & 3;
    const int gg = jj >> 3, uu = jj & 7;
    const float* gptr = gates_in + (size_t)bb * (4 * HH) + gg * HH + u0 + uu;
    float cstate = 0.f;      // valid for tid < 32 (cell lane owns (u=tid>>2, b=tid&3))

    for (int t = 0; t < TT; ++t) {
        // prefetch this step's gate input (latency hides under the barrier wait)
        float gin = 0.f;
        if (tid < 128) gin = __ldg(gptr + (size_t)t * BB * 4 * HH);

        if (t > 0) {
            if (tid == 0) {
                unsigned tgt = (unsigned)NBLK * (unsigned)t;
                unsigned v;
                do {
                    asm volatile("ld.acquire.gpu.global.u32 %0, [%1];"
                                 : "=r"(v) : "l"(counter));
                } while (v < tgt);
            }
            __syncthreads();                      // entry sync: joins warp0 after cell(t-1)
            if (tid < 128) ginsh[tid] = gin;      // safe: warp0 past cell(t-1) reads
            const float* hp = hout + (size_t)(t - 1) * BB * HH;
            for (int i = tid * 4; i < BB * HH; i += 1024)
                *(float4*)(hsh + i) = __ldcg((const float4*)(hp + i));
            __syncthreads();
        } else {
            if (tid < 128) ginsh[tid] = gin;
            __syncthreads();
        }

        // packed f32x2 partial dots: acc.xy[b] += Wreg[k,k+1] * h[b][k,k+1]
        {
            const float* hb = hsh + (ks << 7);
            ull a0 = 0ull, a1 = 0ull, a2 = 0ull, a3 = 0ull;
#pragma unroll
            for (int i = 0; i < 32; ++i) {       // i = k/4 within slice
                const int k = i * 4;
                ulonglong2 x0 = *(const ulonglong2*)(hb + k);
                ulonglong2 x1 = *(const ulonglong2*)(hb + 1024 + k);
                ulonglong2 x2 = *(const ulonglong2*)(hb + 2048 + k);
                ulonglong2 x3 = *(const ulonglong2*)(hb + 3072 + k);
                ull w0 = wreg[i * 2], w1 = wreg[i * 2 + 1];
                FMA2(a0, w0, x0.x); FMA2(a0, w1, x0.y);
                FMA2(a1, w0, x1.x); FMA2(a1, w1, x1.y);
                FMA2(a2, w0, x2.x); FMA2(a2, w1, x2.y);
                FMA2(a3, w0, x3.x); FMA2(a3, w1, x3.y);
            }
            *(float4*)(part + ((ks << 5) + j) * 4) =
                make_float4(f2sum(a0), f2sum(a1), f2sum(a2), f2sum(a3));
        }
        __syncthreads();     // parts ready (warps 1-7 run ahead to next entry sync)

        // warp 0: merged reduce + cell + store + early release
        if (tid < 32) {
            int u = tid >> 2, b = tid & 3;
            float s[4];
#pragma unroll
            for (int g = 0; g < 4; ++g) {
                int row = g * 8 + u;
                float acc = ginsh[(g << 5) + (u << 2) + b];
#pragma unroll
                for (int q = 0; q < 8; ++q)
                    acc += part[((q << 5) + row) * 4 + b];
                s[g] = acc;
            }
            float cn = sigm_f(s[1]) * cstate + sigm_f(s[0]) * tanh_f(s[2]);
            float hn = sigm_f(s[3]) * tanh_f(cn);
            cstate = cn;
            hout[((size_t)t * BB + b) * HH + u0 + u] = hn;
            __syncwarp();    // all 32 h-stores ordered before the release below
            if (tid == 0) {
                asm volatile("red.release.gpu.global.add.u32 [%0], %1;"
                             :: "l"(counter), "r"(1u) : "memory");
            }
        }
    }
}

__global__ void reset_counter_kernel(unsigned* c)
{
    if (threadIdx.x == 0) *c = 0u;
}

// ======================= LayerNorm -> bf16 split, batch-major =======================
__global__ __launch_bounds__(256) void layernorm_kernel(
    const float* __restrict__ in, const float* __restrict__ w,
    const float* __restrict__ bv, __nv_bfloat16* __restrict__ oh,
    __nv_bfloat16* __restrict__ ol)
{
    int t = blockIdx.x, b = blockIdx.y;
    const float* x = in + ((size_t)t * BB + b) * HH;
    size_t orow = ((size_t)b * TT + t) * HH;
    __shared__ float row[HH];
    __shared__ float red[8];
    __shared__ float stat[2];
    int tid = threadIdx.x;

    float s = 0.f;
    for (int i = tid; i < HH; i += 256) { float v = x[i]; row[i] = v; s += v; }
#pragma unroll
    for (int off = 16; off; off >>= 1) s += __shfl_xor_sync(0xffffffffu, s, off);
    if ((tid & 31) == 0) red[tid >> 5] = s;
    __syncthreads();
    if (tid == 0) {
        float tot = 0.f;
        for (int i = 0; i < 8; ++i) tot += red[i];
        stat[0] = tot * (1.f / HH);
    }
    __syncthreads();
    float mu = stat[0];
    float v2 = 0.f;
    for (int i = tid; i < HH; i += 256) { float d = row[i] - mu; v2 += d * d; }
#pragma unroll
    for (int off = 16; off; off >>= 1) v2 += __shfl_xor_sync(0xffffffffu, v2, off);
    __syncthreads();
    if ((tid & 31) == 0) red[tid >> 5] = v2;
    __syncthreads();
    if (tid == 0) {
        float tot = 0.f;
        for (int i = 0; i < 8; ++i) tot += red[i];
        stat[1] = rsqrtf(tot * (1.f / HH) + 1e-5f);
    }
    __syncthreads();
    float inv = stat[1];
    for (int i = tid; i < HH; i += 256) {
        float v = (row[i] - mu) * inv * w[i] + bv[i];
        __nv_bfloat16 hi, lo;
        split_bf16(v, hi, lo);
        oh[orow + i] = hi;
        ol[orow + i] = lo;
    }
}

// ======================= launch =======================
extern "C" void kernel_launch(void* const* d_in, const int* in_sizes, int n_in,
                              void* d_out, int out_size)
{
    (void)in_sizes; (void)n_in; (void)out_size;
    const int*   ids = (const int*)d_in[0];
    const float* we  = (const float*)d_in[1];
    const float* pe  = (const float*)d_in[2];
    const float* Wih = (const float*)d_in[3];
    const float* Whh = (const float*)d_in[4];
    const float* bih = (const float*)d_in[5];
    const float* bhh = (const float*)d_in[6];
    const float* lnw = (const float*)d_in[7];
    const float* lnb = (const float*)d_in[8];
    float* out = (float*)d_out;

    __nv_bfloat16 *weh, *wel, *wihh, *wihl, *fh, *fl, *h0h, *h0l, *xnh, *xnl;
    float *gates, *h0, *h1; unsigned* counter;
    cudaGetSymbolAddress((void**)&weh,  g_weh);
    cudaGetSymbolAddress((void**)&wel,  g_wel);
    cudaGetSymbolAddress((void**)&wihh, g_wihh);
    cudaGetSymbolAddress((void**)&wihl, g_wihl);
    cudaGetSymbolAddress((void**)&fh,   g_fh);
    cudaGetSymbolAddress((void**)&fl,   g_fl);
    cudaGetSymbolAddress((void**)&h0h,  g_h0h);
    cudaGetSymbolAddress((void**)&h0l,  g_h0l);
    cudaGetSymbolAddress((void**)&xnh,  g_xnh);
    cudaGetSymbolAddress((void**)&xnl,  g_xnl);
    cudaGetSymbolAddress((void**)&gates, g_gates);
    cudaGetSymbolAddress((void**)&h0,    g_h0);
    cudaGetSymbolAddress((void**)&h1,    g_h1);
    cudaGetSymbolAddress((void**)&counter, g_counter);

    size_t lsmem = (size_t)(4 * 1024 + 8 * 32 * 4 + 128) * sizeof(float);
    cudaFuncSetAttribute(lstm_layer_kernel,
                         cudaFuncAttributeMaxDynamicSharedMemorySize, (int)lsmem);
    cudaFuncSetAttribute(gemm_hmma_kernel,
                         cudaFuncAttributeMaxDynamicSharedMemorySize, GSMEM);

    // weight/input splits
    convsplit_kernel<<<(VV * HH / 4 + 255) / 256, 256>>>(we, weh, wel, VV * HH / 4);
    convsplit_kernel<<<(2 * 4 * HH * HH / 4 + 255) / 256, 256>>>(Wih, wihh, wihl,
                                                                 2 * 4 * HH * HH / 4);
    embed_kernel<<<dim3(TT, BB), 256>>>(ids, we, pe, fh, fl);

    // layer0 input gates
    gemm_hmma_kernel<<<dim3(4 * HH / 128, TT * BB / 128), 256, GSMEM>>>(
        fh, fl, wihh, wihl, bih, bhh, gates, 4 * HH);
    reset_counter_kernel<<<1, 32>>>(counter);
    lstm_layer_kernel<<<NBLK, 256, lsmem>>>(gates, Whh, h0, counter);

    // layer1
    convsplit_kernel<<<(TT * BB * HH / 4 + 255) / 256, 256>>>(h0, h0h, h0l, TT * BB * HH / 4);
    gemm_hmma_kernel<<<dim3(4 * HH / 128, TT * BB / 128), 256, GSMEM>>>(
        h0h, h0l, wihh + (size_t)4 * HH * HH, wihl + (size_t)4 * HH * HH,
        bih + 4 * HH, bhh + 4 * HH, gates, 4 * HH);
    reset_counter_kernel<<<1, 32>>>(counter);
    lstm_layer_kernel<<<NBLK, 256, lsmem>>>(gates, Whh + (size_t)4 * HH * HH, h1, counter);

    // layernorm + head
    layernorm_kernel<<<dim3(TT, BB), 256>>>(h1, lnw, lnb, xnh, xnl);
    gemm_hmma_kernel<<<dim3(VV / 128, TT * BB / 128), 256, GSMEM>>>(
        xnh, xnl, weh, wel, nullptr, nullptr, out, VV);
}